// round 4
// baseline (speedup 1.0000x reference)
#include <cuda_runtime.h>

#define VOCAB 50257
#define EMBED 128
#define BATCH 64
#define NSENT 50
#define TC 20
#define TQ 20
#define NHOPS 3

// Scratch (device global — no allocation allowed)
__device__ float g_u[BATCH * EMBED];

// ---------------------------------------------------------------------------
// Kernel 1: fused embedding sums + 3 attention hops. One block per batch row.
// 512 threads = 16 warps. m[50][128], c[50][128] live in dynamic smem.
// Phase A: 51 gather tasks (50 sentences + 1 question) round-robin over warps;
//          lane l covers dims [4l,4l+4) via float4, tokens broadcast via shfl.
// Phase B: 3 hops entirely in smem (score / softmax / aggregate).
// ---------------------------------------------------------------------------
__global__ void __launch_bounds__(512) fused_kernel(
        const int* __restrict__ stories,
        const int* __restrict__ questions,
        const int* __restrict__ masks,
        const float* __restrict__ WA,
        const float* __restrict__ WB,
        const float* __restrict__ WC,
        const float* __restrict__ WAT,
        const float* __restrict__ WCT) {
    extern __shared__ float sm[];
    float* m_s = sm;                    // 50*128
    float* c_s = sm + NSENT * EMBED;    // 50*128
    float* u_s = sm + 2 * NSENT * EMBED;  // 128
    float* sc = u_s + EMBED;              // 64

    int b = blockIdx.x;
    int tid = threadIdx.x;
    int w = tid >> 5, lane = tid & 31;

    // ---- Phase A: gathers ----
    for (int task = w; task < NSENT + 1; task += 16) {
        if (task < NSENT) {
            int row = b * NSENT + task;
            int mytok = (lane < TC) ? stories[row * TC + lane] : 0;
            int mymsk = (lane < TC) ? masks[row * TC + lane] : 1;
            unsigned ball = __ballot_sync(0xffffffffu, (lane < TC) && (mymsk == 0));
            int te = (ball != 0u) ? (task + 1) : 0;

            float4 ma = *(const float4*)&WAT[te * EMBED + lane * 4];
            float4 ca = *(const float4*)&WCT[te * EMBED + lane * 4];
#pragma unroll
            for (int t = 0; t < TC; t++) {
                int tk = __shfl_sync(0xffffffffu, mytok, t);
                float4 a = *(const float4*)&WA[(size_t)tk * EMBED + lane * 4];
                float4 c = *(const float4*)&WC[(size_t)tk * EMBED + lane * 4];
                ma.x += a.x; ma.y += a.y; ma.z += a.z; ma.w += a.w;
                ca.x += c.x; ca.y += c.y; ca.z += c.z; ca.w += c.w;
            }
            *(float4*)&m_s[task * EMBED + lane * 4] = ma;
            *(float4*)&c_s[task * EMBED + lane * 4] = ca;
        } else {
            int myq = (lane < TQ) ? questions[b * TQ + lane] : 0;
            float4 u = make_float4(0.f, 0.f, 0.f, 0.f);
#pragma unroll
            for (int t = 0; t < TQ; t++) {
                int tk = __shfl_sync(0xffffffffu, myq, t);
                float4 a = *(const float4*)&WB[(size_t)tk * EMBED + lane * 4];
                u.x += a.x; u.y += a.y; u.z += a.z; u.w += a.w;
            }
            *(float4*)&u_s[lane * 4] = u;
        }
    }
    __syncthreads();

    // ---- Phase B: hops ----
    for (int hop = 0; hop < NHOPS; hop++) {
        // scores: warp w handles n = w, w+16, w+32 (w+48 doesn't exist; n<50)
        float4 uv = *(const float4*)&u_s[lane * 4];
        for (int n = w; n < NSENT; n += 16) {
            float4 mv = *(const float4*)&m_s[n * EMBED + lane * 4];
            float p = mv.x * uv.x + mv.y * uv.y + mv.z * uv.z + mv.w * uv.w;
#pragma unroll
            for (int o = 16; o > 0; o >>= 1) p += __shfl_xor_sync(0xffffffffu, p, o);
            if (lane == 0) sc[n] = p;
        }
        __syncthreads();
        if (w == 0) {
            float v0 = (lane < NSENT) ? sc[lane] : -1e30f;
            float v1 = (lane + 32 < NSENT) ? sc[lane + 32] : -1e30f;
            float mx = fmaxf(v0, v1);
#pragma unroll
            for (int o = 16; o > 0; o >>= 1) mx = fmaxf(mx, __shfl_xor_sync(0xffffffffu, mx, o));
            float e0 = (lane < NSENT) ? expf(v0 - mx) : 0.f;
            float e1 = (lane + 32 < NSENT) ? expf(v1 - mx) : 0.f;
            float s = e0 + e1;
#pragma unroll
            for (int o = 16; o > 0; o >>= 1) s += __shfl_xor_sync(0xffffffffu, s, o);
            float inv = 1.f / s;
            if (lane < NSENT) sc[lane] = e0 * inv;
            if (lane + 32 < NSENT) sc[lane + 32] = e1 * inv;
        }
        __syncthreads();
        if (tid < EMBED) {
            float o_acc = 0.f;
#pragma unroll 10
            for (int n = 0; n < NSENT; n++)
                o_acc += c_s[n * EMBED + tid] * sc[n];
            u_s[tid] += o_acc;
        }
        __syncthreads();
    }
    if (tid < EMBED) g_u[b * EMBED + tid] = u_s[tid];
}

// ---------------------------------------------------------------------------
// Kernel 2: logits = u @ W_lin^T + b_lin with packed fma.rn.f32x2.
// One vocab row per thread, all 64 batches as 32 packed batch-pairs (64 regs).
// 393 blocks x 128 threads -> ~2.7 blocks/SM, no wave cliff. Stores coalesced.
// ---------------------------------------------------------------------------
__device__ __forceinline__ unsigned long long pack2(float a, float b) {
    unsigned long long r;
    asm("mov.b64 %0, {%1, %2};" : "=l"(r) : "f"(a), "f"(b));
    return r;
}
__device__ __forceinline__ unsigned long long fma2(unsigned long long a,
                                                   unsigned long long b,
                                                   unsigned long long c) {
    unsigned long long d;
    asm("fma.rn.f32x2 %0, %1, %2, %3;" : "=l"(d) : "l"(a), "l"(b), "l"(c));
    return d;
}
__device__ __forceinline__ void unpack2(unsigned long long v, float& lo, float& hi) {
    asm("mov.b64 {%0, %1}, %2;" : "=f"(lo), "=f"(hi) : "l"(v));
}

__global__ void __launch_bounds__(128) logits_kernel(const float* __restrict__ W,
                                                     const float* __restrict__ bias,
                                                     float* __restrict__ out) {
    // up[j][p]: j = k-pair (2j, 2j+1), p = batch-pair (2p, 2p+1)
    // up[j][p].x = {u[2p][2j],   u[2p+1][2j]}
    // up[j][p].y = {u[2p][2j+1], u[2p+1][2j+1]}
    __shared__ ulonglong2 up[64][32];
    for (int e = threadIdx.x; e < 64 * 32; e += 128) {
        int j = e >> 5, p = e & 31;
        ulonglong2 t;
        t.x = pack2(g_u[(2 * p) * EMBED + 2 * j], g_u[(2 * p + 1) * EMBED + 2 * j]);
        t.y = pack2(g_u[(2 * p) * EMBED + 2 * j + 1], g_u[(2 * p + 1) * EMBED + 2 * j + 1]);
        up[j][p] = t;
    }
    __syncthreads();

    int v = blockIdx.x * 128 + threadIdx.x;
    bool valid = (v < VOCAB);
    int vc = valid ? v : (VOCAB - 1);  // clamp for loads; stores predicated

    unsigned long long acc[32];
#pragma unroll
    for (int p = 0; p < 32; p++) acc[p] = 0ull;

    const float4* wrow = (const float4*)(W + (size_t)vc * EMBED);

#pragma unroll 2
    for (int jq = 0; jq < 32; jq++) {  // covers k = 4jq .. 4jq+3
        float4 a = wrow[jq];
        unsigned long long a0 = pack2(a.x, a.x), a1 = pack2(a.y, a.y);
        unsigned long long a2 = pack2(a.z, a.z), a3 = pack2(a.w, a.w);
#pragma unroll
        for (int p = 0; p < 32; p++) {
            ulonglong2 t0 = up[2 * jq][p];
            ulonglong2 t1 = up[2 * jq + 1][p];
            acc[p] = fma2(a0, t0.x, acc[p]);
            acc[p] = fma2(a1, t0.y, acc[p]);
            acc[p] = fma2(a2, t1.x, acc[p]);
            acc[p] = fma2(a3, t1.y, acc[p]);
        }
    }

    if (!valid) return;
    float bl = bias[v];
#pragma unroll
    for (int p = 0; p < 32; p++) {
        float lo, hi;
        unpack2(acc[p], lo, hi);
        out[(size_t)(2 * p) * VOCAB + v] = lo + bl;
        out[(size_t)(2 * p + 1) * VOCAB + v] = hi + bl;
    }
}

extern "C" void kernel_launch(void* const* d_in, const int* in_sizes, int n_in,
                              void* d_out, int out_size) {
    const int* stories = (const int*)d_in[0];
    const int* questions = (const int*)d_in[1];
    const int* masks = (const int*)d_in[2];
    const float* WA = (const float*)d_in[3];
    const float* WB = (const float*)d_in[4];
    const float* WC = (const float*)d_in[5];
    const float* WAT = (const float*)d_in[6];
    const float* WCT = (const float*)d_in[7];
    const float* Wlin = (const float*)d_in[8];
    const float* blin = (const float*)d_in[9];
    float* out = (float*)d_out;

    const int smem_bytes = (2 * NSENT * EMBED + EMBED + 64) * (int)sizeof(float);  // 51968
    cudaFuncSetAttribute(fused_kernel, cudaFuncAttributeMaxDynamicSharedMemorySize,
                         smem_bytes);
    fused_kernel<<<BATCH, 512, smem_bytes>>>(stories, questions, masks,
                                             WA, WB, WC, WAT, WCT);
    logits_kernel<<<(VOCAB + 127) / 128, 128>>>(Wlin, blin, out);
}

// round 5
// speedup vs baseline: 1.1926x; 1.1926x over previous
#include <cuda_runtime.h>

#define VOCAB 50257
#define EMBED 128
#define BATCH 64
#define NSENT 50
#define TC 20
#define TQ 20
#define NHOPS 3

// Scratch (device global — no allocation allowed)
__device__ float g_u[BATCH * EMBED];
__device__ float g_m[BATCH * NSENT * EMBED];
__device__ float g_c[BATCH * NSENT * EMBED];

// ---------------------------------------------------------------------------
// Kernel 1: embedding sums. One WARP per sentence (or question). (R3, 11.3us)
// ---------------------------------------------------------------------------
__global__ void __launch_bounds__(128) embed_kernel(
        const int* __restrict__ stories,
        const int* __restrict__ questions,
        const int* __restrict__ masks,
        const float* __restrict__ WA,
        const float* __restrict__ WB,
        const float* __restrict__ WC,
        const float* __restrict__ WAT,
        const float* __restrict__ WCT) {
    int gwarp = (blockIdx.x * blockDim.x + threadIdx.x) >> 5;
    int lane = threadIdx.x & 31;

    if (gwarp < BATCH * NSENT) {
        int s = gwarp % NSENT;
        int mytok = (lane < TC) ? stories[gwarp * TC + lane] : 0;
        int mymsk = (lane < TC) ? masks[gwarp * TC + lane] : 1;
        unsigned ball = __ballot_sync(0xffffffffu, (lane < TC) && (mymsk == 0));
        int te = (ball != 0u) ? (s + 1) : 0;

        float4 ma = *(const float4*)&WAT[te * EMBED + lane * 4];
        float4 ca = *(const float4*)&WCT[te * EMBED + lane * 4];
#pragma unroll
        for (int t = 0; t < TC; t++) {
            int tk = __shfl_sync(0xffffffffu, mytok, t);
            float4 a = *(const float4*)&WA[(size_t)tk * EMBED + lane * 4];
            float4 c = *(const float4*)&WC[(size_t)tk * EMBED + lane * 4];
            ma.x += a.x; ma.y += a.y; ma.z += a.z; ma.w += a.w;
            ca.x += c.x; ca.y += c.y; ca.z += c.z; ca.w += c.w;
        }
        *(float4*)&g_m[(size_t)gwarp * EMBED + lane * 4] = ma;
        *(float4*)&g_c[(size_t)gwarp * EMBED + lane * 4] = ca;
    } else if (gwarp < BATCH * NSENT + BATCH) {
        int b = gwarp - BATCH * NSENT;
        int myq = (lane < TQ) ? questions[b * TQ + lane] : 0;
        float4 u = make_float4(0.f, 0.f, 0.f, 0.f);
#pragma unroll
        for (int t = 0; t < TQ; t++) {
            int tk = __shfl_sync(0xffffffffu, myq, t);
            float4 a = *(const float4*)&WB[(size_t)tk * EMBED + lane * 4];
            u.x += a.x; u.y += a.y; u.z += a.z; u.w += a.w;
        }
        *(float4*)&g_u[b * EMBED + lane * 4] = u;
    }
}

// ---------------------------------------------------------------------------
// Kernel 2: 3 attention hops. One block per batch row, 128 threads. (R3)
// ---------------------------------------------------------------------------
__global__ void hops_kernel() {
    int b = blockIdx.x;
    int tid = threadIdx.x;
    int w = tid >> 5, lane = tid & 31;
    __shared__ float u_s[EMBED];
    __shared__ float sc[64];
    u_s[tid] = g_u[b * EMBED + tid];
    __syncthreads();
    for (int hop = 0; hop < NHOPS; hop++) {
        float4 uv = *(const float4*)&u_s[lane * 4];
        for (int n = w; n < NSENT; n += 4) {
            float4 mv = *(const float4*)&g_m[((size_t)(b * NSENT + n)) * EMBED + lane * 4];
            float p = mv.x * uv.x + mv.y * uv.y + mv.z * uv.z + mv.w * uv.w;
#pragma unroll
            for (int o = 16; o > 0; o >>= 1) p += __shfl_xor_sync(0xffffffffu, p, o);
            if (lane == 0) sc[n] = p;
        }
        __syncthreads();
        if (w == 0) {
            float v0 = (lane < NSENT) ? sc[lane] : -1e30f;
            float v1 = (lane + 32 < NSENT) ? sc[lane + 32] : -1e30f;
            float mx = fmaxf(v0, v1);
#pragma unroll
            for (int o = 16; o > 0; o >>= 1) mx = fmaxf(mx, __shfl_xor_sync(0xffffffffu, mx, o));
            float e0 = (lane < NSENT) ? expf(v0 - mx) : 0.f;
            float e1 = (lane + 32 < NSENT) ? expf(v1 - mx) : 0.f;
            float s = e0 + e1;
#pragma unroll
            for (int o = 16; o > 0; o >>= 1) s += __shfl_xor_sync(0xffffffffu, s, o);
            float inv = 1.f / s;
            if (lane < NSENT) sc[lane] = e0 * inv;
            if (lane + 32 < NSENT) sc[lane + 32] = e1 * inv;
        }
        __syncthreads();
        float o_acc = 0.f;
#pragma unroll 10
        for (int n = 0; n < NSENT; n++)
            o_acc += g_c[((size_t)(b * NSENT + n)) * EMBED + tid] * sc[n];
        u_s[tid] += o_acc;
        __syncthreads();
    }
    g_u[b * EMBED + tid] = u_s[tid];
}

// ---------------------------------------------------------------------------
// Kernel 3: logits GEMM, register-tiled, packed fma.rn.f32x2.
// Grid 786 = 393 row-blocks x 2 batch-halves. Block tile: 128 rows x 32 batch.
// Thread (rg 0..15, bg 0..7): rows {4rg..4rg+3, 64+4rg..64+4rg+3},
// batches bh*32 + 4bg..+3. acc = 4 rowpairs x 4 batches u64.
// wp[k][pair] holds W row-pairs packed (u64), XOR-swizzled by (k>>2)&14.
// udup[k][b] holds u duplicated {u,u}. Zero packing movs in the hot loop.
// ---------------------------------------------------------------------------
__device__ __forceinline__ unsigned long long pack2(float a, float b) {
    unsigned long long r;
    asm("mov.b64 %0, {%1, %2};" : "=l"(r) : "f"(a), "f"(b));
    return r;
}
__device__ __forceinline__ unsigned long long fma2(unsigned long long a,
                                                   unsigned long long b,
                                                   unsigned long long c) {
    unsigned long long d;
    asm("fma.rn.f32x2 %0, %1, %2, %3;" : "=l"(d) : "l"(a), "l"(b), "l"(c));
    return d;
}
__device__ __forceinline__ void unpack2(unsigned long long v, float& lo, float& hi) {
    asm("mov.b64 {%0, %1}, %2;" : "=f"(lo), "=f"(hi) : "l"(v));
}

#define ROWBLKS 393  // ceil(VOCAB/128)

__global__ void __launch_bounds__(128) logits_kernel(const float* __restrict__ W,
                                                     const float* __restrict__ bias,
                                                     float* __restrict__ out) {
    extern __shared__ unsigned long long sh[];
    unsigned long long* udup = sh;          // [128 k][32 b]  = 4096 u64 = 32 KB
    unsigned long long* wp = sh + 128 * 32; // [64 k][64 pr]  = 4096 u64 = 32 KB

    int tid = threadIdx.x;
    int rb = blockIdx.x >> 1;
    int bh = blockIdx.x & 1;
    int row0 = rb * 128;

    int rg = tid & 15;
    int bg = tid >> 4;

    // ---- stage udup (one-time): thread t<32 handles batch bh*32+t ----
    if (tid < 32) {
        const float4* ub = (const float4*)&g_u[(bh * 32 + tid) * EMBED];
#pragma unroll 8
        for (int kq = 0; kq < 32; kq++) {
            float4 v = ub[kq];
            udup[(4 * kq + 0) * 32 + tid] = pack2(v.x, v.x);
            udup[(4 * kq + 1) * 32 + tid] = pack2(v.y, v.y);
            udup[(4 * kq + 2) * 32 + tid] = pack2(v.z, v.z);
            udup[(4 * kq + 3) * 32 + tid] = pack2(v.w, v.w);
        }
    }

    unsigned long long acc[4][4];
#pragma unroll
    for (int i = 0; i < 4; i++)
#pragma unroll
        for (int j = 0; j < 4; j++) acc[i][j] = 0ull;

    for (int chunk = 0; chunk < 2; chunk++) {
        if (chunk) __syncthreads();  // readers of previous chunk done
        // ---- stage W chunk (coalesced gmem, swizzled paired smem) ----
#pragma unroll
        for (int i = 0; i < 16; i++) {
            int s = tid + 128 * i;
            int row = s >> 4, kq = s & 15;
            int grow = row0 + row;
            if (grow > VOCAB - 1) grow = VOCAB - 1;
            float4 v = *(const float4*)(W + (size_t)grow * EMBED + chunk * 64 + kq * 4);
            int pp = (row >> 1) ^ (kq & 14);
            int hl = row & 1;
            ((float*)&wp[(4 * kq + 0) * 64 + pp])[hl] = v.x;
            ((float*)&wp[(4 * kq + 1) * 64 + pp])[hl] = v.y;
            ((float*)&wp[(4 * kq + 2) * 64 + pp])[hl] = v.z;
            ((float*)&wp[(4 * kq + 3) * 64 + pp])[hl] = v.w;
        }
        __syncthreads();

        const unsigned long long* ubase = udup + (chunk * 64) * 32 + 4 * bg;
        // ---- compute 64 k-steps ----
#pragma unroll 4
        for (int k = 0; k < 64; k++) {
            int wsw = (k >> 2) & 14;
            const unsigned long long* wk = wp + k * 64;
            ulonglong2 wa = *(const ulonglong2*)(wk + ((2 * rg) ^ wsw));
            ulonglong2 wb2 = *(const ulonglong2*)(wk + (32 + ((2 * rg) ^ wsw)));
            ulonglong2 ua = *(const ulonglong2*)(ubase + k * 32);
            ulonglong2 uc = *(const ulonglong2*)(ubase + k * 32 + 2);

            acc[0][0] = fma2(wa.x, ua.x, acc[0][0]);
            acc[0][1] = fma2(wa.x, ua.y, acc[0][1]);
            acc[0][2] = fma2(wa.x, uc.x, acc[0][2]);
            acc[0][3] = fma2(wa.x, uc.y, acc[0][3]);
            acc[1][0] = fma2(wa.y, ua.x, acc[1][0]);
            acc[1][1] = fma2(wa.y, ua.y, acc[1][1]);
            acc[1][2] = fma2(wa.y, uc.x, acc[1][2]);
            acc[1][3] = fma2(wa.y, uc.y, acc[1][3]);
            acc[2][0] = fma2(wb2.x, ua.x, acc[2][0]);
            acc[2][1] = fma2(wb2.x, ua.y, acc[2][1]);
            acc[2][2] = fma2(wb2.x, uc.x, acc[2][2]);
            acc[2][3] = fma2(wb2.x, uc.y, acc[2][3]);
            acc[3][0] = fma2(wb2.y, ua.x, acc[3][0]);
            acc[3][1] = fma2(wb2.y, ua.y, acc[3][1]);
            acc[3][2] = fma2(wb2.y, uc.x, acc[3][2]);
            acc[3][3] = fma2(wb2.y, uc.y, acc[3][3]);
        }
    }

    // ---- epilogue: +bias, guarded scalar stores ----
    // acc[0]: rows (row0+4rg, +1); acc[1]: (+2, +3);
    // acc[2]: (row0+64+4rg, +1); acc[3]: (+2, +3)
    int rbase[4] = {row0 + 4 * rg, row0 + 4 * rg + 2,
                    row0 + 64 + 4 * rg, row0 + 64 + 4 * rg + 2};
#pragma unroll
    for (int i = 0; i < 4; i++) {
        int r_lo = rbase[i], r_hi = rbase[i] + 1;
        bool v_lo = (r_lo < VOCAB), v_hi = (r_hi < VOCAB);
        float blo = v_lo ? bias[r_lo] : 0.f;
        float bhi = v_hi ? bias[r_hi] : 0.f;
#pragma unroll
        for (int j = 0; j < 4; j++) {
            int b = bh * 32 + 4 * bg + j;
            float lo, hi;
            unpack2(acc[i][j], lo, hi);
            if (v_lo) out[(size_t)b * VOCAB + r_lo] = lo + blo;
            if (v_hi) out[(size_t)b * VOCAB + r_hi] = hi + bhi;
        }
    }
}

extern "C" void kernel_launch(void* const* d_in, const int* in_sizes, int n_in,
                              void* d_out, int out_size) {
    const int* stories = (const int*)d_in[0];
    const int* questions = (const int*)d_in[1];
    const int* masks = (const int*)d_in[2];
    const float* WA = (const float*)d_in[3];
    const float* WB = (const float*)d_in[4];
    const float* WC = (const float*)d_in[5];
    const float* WAT = (const float*)d_in[6];
    const float* WCT = (const float*)d_in[7];
    const float* Wlin = (const float*)d_in[8];
    const float* blin = (const float*)d_in[9];
    float* out = (float*)d_out;

    int total_warps = BATCH * NSENT + BATCH;
    int embed_blocks = (total_warps * 32 + 127) / 128;
    embed_kernel<<<embed_blocks, 128>>>(stories, questions, masks, WA, WB, WC, WAT, WCT);
    hops_kernel<<<BATCH, EMBED>>>();

    const int lg_smem = 64 * 1024;
    cudaFuncSetAttribute(logits_kernel, cudaFuncAttributeMaxDynamicSharedMemorySize,
                         lg_smem);
    logits_kernel<<<ROWBLKS * 2, 128, lg_smem>>>(Wlin, blin, out);
}

// round 7
// speedup vs baseline: 1.7206x; 1.4428x over previous
#include <cuda_runtime.h>
#include <cstdint>

#define VOCAB 50257
#define EMBED 128
#define BATCH 64
#define NSENT 50
#define TC 20
#define TQ 20
#define NHOPS 3

// Scratch (device global — no allocation allowed)
__device__ float g_u[BATCH * EMBED];
__device__ float g_m[BATCH * NSENT * EMBED];
__device__ float g_c[BATCH * NSENT * EMBED];

// ---------------------------------------------------------------------------
// Kernel 1: embedding sums. One WARP per sentence (or question).
// ---------------------------------------------------------------------------
__global__ void __launch_bounds__(128) embed_kernel(
        const int* __restrict__ stories,
        const int* __restrict__ questions,
        const int* __restrict__ masks,
        const float* __restrict__ WA,
        const float* __restrict__ WB,
        const float* __restrict__ WC,
        const float* __restrict__ WAT,
        const float* __restrict__ WCT) {
    int gwarp = (blockIdx.x * blockDim.x + threadIdx.x) >> 5;
    int lane = threadIdx.x & 31;

    if (gwarp < BATCH * NSENT) {
        int s = gwarp % NSENT;
        int mytok = (lane < TC) ? stories[gwarp * TC + lane] : 0;
        int mymsk = (lane < TC) ? masks[gwarp * TC + lane] : 1;
        unsigned ball = __ballot_sync(0xffffffffu, (lane < TC) && (mymsk == 0));
        int te = (ball != 0u) ? (s + 1) : 0;

        float4 ma = *(const float4*)&WAT[te * EMBED + lane * 4];
        float4 ca = *(const float4*)&WCT[te * EMBED + lane * 4];
#pragma unroll
        for (int t = 0; t < TC; t++) {
            int tk = __shfl_sync(0xffffffffu, mytok, t);
            float4 a = *(const float4*)&WA[(size_t)tk * EMBED + lane * 4];
            float4 c = *(const float4*)&WC[(size_t)tk * EMBED + lane * 4];
            ma.x += a.x; ma.y += a.y; ma.z += a.z; ma.w += a.w;
            ca.x += c.x; ca.y += c.y; ca.z += c.z; ca.w += c.w;
        }
        *(float4*)&g_m[(size_t)gwarp * EMBED + lane * 4] = ma;
        *(float4*)&g_c[(size_t)gwarp * EMBED + lane * 4] = ca;
    } else if (gwarp < BATCH * NSENT + BATCH) {
        int b = gwarp - BATCH * NSENT;
        int myq = (lane < TQ) ? questions[b * TQ + lane] : 0;
        float4 u = make_float4(0.f, 0.f, 0.f, 0.f);
#pragma unroll
        for (int t = 0; t < TQ; t++) {
            int tk = __shfl_sync(0xffffffffu, myq, t);
            float4 a = *(const float4*)&WB[(size_t)tk * EMBED + lane * 4];
            u.x += a.x; u.y += a.y; u.z += a.z; u.w += a.w;
        }
        *(float4*)&g_u[b * EMBED + lane * 4] = u;
    }
}

// ---------------------------------------------------------------------------
// Kernel 2: 3 attention hops. One block per batch row, 128 threads.
// ---------------------------------------------------------------------------
__global__ void hops_kernel() {
    int b = blockIdx.x;
    int tid = threadIdx.x;
    int w = tid >> 5, lane = tid & 31;
    __shared__ float u_s[EMBED];
    __shared__ float sc[64];
    u_s[tid] = g_u[b * EMBED + tid];
    __syncthreads();
    for (int hop = 0; hop < NHOPS; hop++) {
        float4 uv = *(const float4*)&u_s[lane * 4];
        for (int n = w; n < NSENT; n += 4) {
            float4 mv = *(const float4*)&g_m[((size_t)(b * NSENT + n)) * EMBED + lane * 4];
            float p = mv.x * uv.x + mv.y * uv.y + mv.z * uv.z + mv.w * uv.w;
#pragma unroll
            for (int o = 16; o > 0; o >>= 1) p += __shfl_xor_sync(0xffffffffu, p, o);
            if (lane == 0) sc[n] = p;
        }
        __syncthreads();
        if (w == 0) {
            float v0 = (lane < NSENT) ? sc[lane] : -1e30f;
            float v1 = (lane + 32 < NSENT) ? sc[lane + 32] : -1e30f;
            float mx = fmaxf(v0, v1);
#pragma unroll
            for (int o = 16; o > 0; o >>= 1) mx = fmaxf(mx, __shfl_xor_sync(0xffffffffu, mx, o));
            float e0 = (lane < NSENT) ? expf(v0 - mx) : 0.f;
            float e1 = (lane + 32 < NSENT) ? expf(v1 - mx) : 0.f;
            float s = e0 + e1;
#pragma unroll
            for (int o = 16; o > 0; o >>= 1) s += __shfl_xor_sync(0xffffffffu, s, o);
            float inv = 1.f / s;
            if (lane < NSENT) sc[lane] = e0 * inv;
            if (lane + 32 < NSENT) sc[lane + 32] = e1 * inv;
        }
        __syncthreads();
        float o_acc = 0.f;
#pragma unroll 10
        for (int n = 0; n < NSENT; n++)
            o_acc += g_c[((size_t)(b * NSENT + n)) * EMBED + tid] * sc[n];
        u_s[tid] += o_acc;
        __syncthreads();
    }
    g_u[b * EMBED + tid] = u_s[tid];
}

// ---------------------------------------------------------------------------
// Kernel 3: logits via warp-level tf32 mma.sync (m16n8k8, fp32 accumulate).
// Per CTA (128 thr): D[128 vocab x 64 batch]. Per warp: 32 rows x 64 batch.
// B = u staged tf32 in smem (pad 132 -> conflict-free frag loads).
// A = W fragments from gmem (L1-resident across k loop) + cvt.rna.tf32.
// ---------------------------------------------------------------------------
__device__ __forceinline__ uint32_t tf32b(float x) {
    float r;
    asm("cvt.rna.tf32.f32 %0, %1;" : "=f"(r) : "f"(x));
    return __float_as_uint(r);
}
__device__ __forceinline__ void mma_tf32(float* c, const uint32_t* a,
                                         uint32_t b0, uint32_t b1) {
    asm volatile(
        "mma.sync.aligned.m16n8k8.row.col.f32.tf32.tf32.f32 "
        "{%0,%1,%2,%3}, {%4,%5,%6,%7}, {%8,%9}, {%0,%1,%2,%3};"
        : "+f"(c[0]), "+f"(c[1]), "+f"(c[2]), "+f"(c[3])
        : "r"(a[0]), "r"(a[1]), "r"(a[2]), "r"(a[3]), "r"(b0), "r"(b1));
}

__global__ void __launch_bounds__(128) logits_mma_kernel(
        const float* __restrict__ W,
        const float* __restrict__ bias,
        float* __restrict__ out) {
    __shared__ uint32_t us[64][132];  // u in tf32 bits, padded row

    int tid = threadIdx.x;
    int wid = tid >> 5, lane = tid & 31;
    int gid = lane >> 2, tig = lane & 3;

    // ---- stage u -> tf32 smem ----
    for (int e = tid; e < 64 * 32; e += 128) {
        int row = e >> 5, q = e & 31;
        float4 v = *(const float4*)(g_u + row * EMBED + q * 4);
        us[row][q * 4 + 0] = tf32b(v.x);
        us[row][q * 4 + 1] = tf32b(v.y);
        us[row][q * 4 + 2] = tf32b(v.z);
        us[row][q * 4 + 3] = tf32b(v.w);
    }
    __syncthreads();

    int row0 = blockIdx.x * 128;
    int rbase = row0 + wid * 32;

    float acc[2][8][4];
#pragma unroll
    for (int i = 0; i < 2; i++)
#pragma unroll
        for (int j = 0; j < 8; j++)
#pragma unroll
            for (int q = 0; q < 4; q++) acc[i][j][q] = 0.f;

#pragma unroll 4
    for (int s = 0; s < 16; s++) {
        int k0 = s * 8 + tig;
        uint32_t a[2][4];
#pragma unroll
        for (int i = 0; i < 2; i++) {
            int rlo = rbase + i * 16 + gid;
            int rhi = rlo + 8;
            if (rlo > VOCAB - 1) rlo = VOCAB - 1;
            if (rhi > VOCAB - 1) rhi = VOCAB - 1;
            a[i][0] = tf32b(__ldg(W + (size_t)rlo * EMBED + k0));
            a[i][1] = tf32b(__ldg(W + (size_t)rhi * EMBED + k0));
            a[i][2] = tf32b(__ldg(W + (size_t)rlo * EMBED + k0 + 4));
            a[i][3] = tf32b(__ldg(W + (size_t)rhi * EMBED + k0 + 4));
        }
#pragma unroll
        for (int j = 0; j < 8; j++) {
            uint32_t b0 = us[j * 8 + gid][k0];
            uint32_t b1 = us[j * 8 + gid][k0 + 4];
            mma_tf32(acc[0][j], a[0], b0, b1);
            mma_tf32(acc[1][j], a[1], b0, b1);
        }
    }

    // ---- epilogue: +bias, scalar stores (out is [batch][vocab]) ----
#pragma unroll
    for (int i = 0; i < 2; i++) {
        int rlo = rbase + i * 16 + gid;
        int rhi = rlo + 8;
        bool vlo = (rlo < VOCAB), vhi = (rhi < VOCAB);
        float blo = vlo ? bias[rlo] : 0.f;
        float bhi = vhi ? bias[rhi] : 0.f;
#pragma unroll
        for (int j = 0; j < 8; j++) {
            int n0 = j * 8 + 2 * tig;
            int n1 = n0 + 1;
            if (vlo) {
                out[(size_t)n0 * VOCAB + rlo] = acc[i][j][0] + blo;
                out[(size_t)n1 * VOCAB + rlo] = acc[i][j][1] + blo;
            }
            if (vhi) {
                out[(size_t)n0 * VOCAB + rhi] = acc[i][j][2] + bhi;
                out[(size_t)n1 * VOCAB + rhi] = acc[i][j][3] + bhi;
            }
        }
    }
}

extern "C" void kernel_launch(void* const* d_in, const int* in_sizes, int n_in,
                              void* d_out, int out_size) {
    const int* stories = (const int*)d_in[0];
    const int* questions = (const int*)d_in[1];
    const int* masks = (const int*)d_in[2];
    const float* WA = (const float*)d_in[3];
    const float* WB = (const float*)d_in[4];
    const float* WC = (const float*)d_in[5];
    const float* WAT = (const float*)d_in[6];
    const float* WCT = (const float*)d_in[7];
    const float* Wlin = (const float*)d_in[8];
    const float* blin = (const float*)d_in[9];
    float* out = (float*)d_out;

    int total_warps = BATCH * NSENT + BATCH;
    int embed_blocks = (total_warps * 32 + 127) / 128;
    embed_kernel<<<embed_blocks, 128>>>(stories, questions, masks, WA, WB, WC, WAT, WCT);
    hops_kernel<<<BATCH, EMBED>>>();

    int nblk = (VOCAB + 127) / 128;  // 393
    logits_mma_kernel<<<nblk, 128>>>(Wlin, blin, out);
}